// round 15
// baseline (speedup 1.0000x reference)
#include <cuda_runtime.h>
#include <cuda_fp16.h>
#include <cstdint>

// ---------------------------------------------------------------------------
// PingHead on sm_103 (legacy mma.sync path, fp16 operands / fp32 accum).
// gi = x @ W_ih^T : M=65536, N=384, K=1024 ; fused GRU-gate epilogue.
// R15: warp-specialized. 512 thr = 12 compute warps (2m x 6n, 32m x 64n tile,
// acc=64) + 4 copy warps (one per SMSP) doing A LDG->cvt->STS and B cp.async
// for chunk kc+2 during MMA(kc). Compute warps: pure ldsm+mma stream.
// 3-stage K64/128B-row ring (172KB, 1 CTA/SM). One __syncthreads per chunk.
// ---------------------------------------------------------------------------

#define M_TILE 64
#define KCHUNKS 16
#define A_ST 8192                            // 64 rows x 128B (fp16)
#define B_ST 49152                           // 384 rows x 128B (fp16)
#define STAGE_BYTES (A_ST + B_ST)            // 57344
#define SMEM_DYN (3 * STAGE_BYTES)           // 172032 ; 1 CTA/SM
#define ROWP 385
// gi (64*385*4 = 98560) fits inside the ring

__device__ __half g_wh[384 * 1024];          // W_ih pre-converted to fp16 (rne)

__device__ __forceinline__ uint32_t smem_u32(const void* p) {
    uint32_t a;
    asm("{ .reg .u64 t; cvta.to.shared.u64 t, %1; cvt.u32.u64 %0, t; }" : "=r"(a) : "l"(p));
    return a;
}

__device__ __forceinline__ void cp_async16(uint32_t dst, const void* src) {
    asm volatile("cp.async.cg.shared.global [%0], [%1], 16;" :: "r"(dst), "l"(src) : "memory");
}
#define CP_COMMIT() asm volatile("cp.async.commit_group;" ::: "memory")
#define CP_WAIT1()  asm volatile("cp.async.wait_group 1;" ::: "memory")
#define CP_WAIT0()  asm volatile("cp.async.wait_group 0;" ::: "memory")

__device__ __forceinline__ void ldsm4(uint32_t* r, uint32_t addr) {
    asm volatile("ldmatrix.sync.aligned.m8n8.x4.shared.b16 {%0,%1,%2,%3}, [%4];"
                 : "=r"(r[0]), "=r"(r[1]), "=r"(r[2]), "=r"(r[3]) : "r"(addr));
}

__device__ __forceinline__ uint32_t pack2h(float a, float b) {
    __half2 h = __floats2half2_rn(a, b);
    return *reinterpret_cast<uint32_t*>(&h);
}

__device__ __forceinline__ void mma_f16(float* d, const uint32_t* a, const uint32_t* b) {
    asm volatile("mma.sync.aligned.m16n8k16.row.col.f32.f16.f16.f32 "
                 "{%0,%1,%2,%3},{%4,%5,%6,%7},{%8,%9},{%0,%1,%2,%3};"
                 : "+f"(d[0]), "+f"(d[1]), "+f"(d[2]), "+f"(d[3])
                 : "r"(a[0]), "r"(a[1]), "r"(a[2]), "r"(a[3]), "r"(b[0]), "r"(b[1]));
}

// --- pre-kernel: W fp32 -> fp16 (rne) ---
__global__ void __launch_bounds__(256) wconv_kernel(const float* __restrict__ w) {
    const int i = (blockIdx.x * 256 + threadIdx.x) * 8;
    const float4 v0 = *reinterpret_cast<const float4*>(w + i);
    const float4 v1 = *reinterpret_cast<const float4*>(w + i + 4);
    uint4 o = make_uint4(pack2h(v0.x, v0.y), pack2h(v0.z, v0.w),
                         pack2h(v1.x, v1.y), pack2h(v1.z, v1.w));
    *reinterpret_cast<uint4*>(g_wh + i) = o;
}

__global__ void __launch_bounds__(512, 1)
ping_head_kernel(const float* __restrict__ x,
                 const float* __restrict__ b_ih,
                 const float* __restrict__ b_hh,
                 const float* __restrict__ lin_w,
                 const float* __restrict__ lin_b,
                 float* __restrict__ out) {
    extern __shared__ char dsm[];

    const int tid = threadIdx.x;
    const int wid = tid >> 5;
    const int lane = tid & 31;
    const int m0 = blockIdx.x * M_TILE;

    const uint32_t sb = smem_u32(dsm);
    char* sb_ptr = dsm;

    const bool is_copy = (wid >= 12);        // wid 12..15 -> SMSP 0..3
    const int ctid = tid - 384;              // copy-thread id 0..127 (valid if is_copy)

    // copy-warp A mapping: 64 rows x 64 f32 / 128 thr = 32 f32 each
    const int a_row = ctid >> 1;             // 0..63
    const int a_half = ctid & 1;             // 0/1 -> 32-float half of the row
    const uint32_t a_xr = (uint32_t)((a_row & 7) << 4);

    auto cpB = [&](int kc) {                 // 3072 x 16B / 128 thr = 24 each
        const int st = kc % 3;
        const int koff = kc * 64;
        const uint32_t bbase = sb + (uint32_t)(st * STAGE_BYTES + A_ST);
#pragma unroll
        for (int ch = 0; ch < 24; ch++) {
            const int bi = ctid + ch * 128;
            const int row = bi >> 3, c = bi & 7;
            const uint32_t doff = (uint32_t)(row * 128) +
                                  (((uint32_t)(c * 16)) ^ ((uint32_t)(row & 7) << 4));
            cp_async16(bbase + doff, g_wh + (size_t)row * 1024 + koff + c * 8);
        }
    };
    auto copyA = [&](int kc) {               // LDG 32 f32 -> cvt -> 4x STS.128
        const int st = kc % 3;
        const float* asrc = x + (size_t)(m0 + a_row) * 1024 + kc * 64 + a_half * 32;
        float4 f[8];
#pragma unroll
        for (int i = 0; i < 8; i++)
            f[i] = *reinterpret_cast<const float4*>(asrc + i * 4);
        char* sA = sb_ptr + st * STAGE_BYTES;
#pragma unroll
        for (int i = 0; i < 4; i++) {
            uint4 o = make_uint4(pack2h(f[2*i].x, f[2*i].y),     pack2h(f[2*i].z, f[2*i].w),
                                 pack2h(f[2*i+1].x, f[2*i+1].y), pack2h(f[2*i+1].z, f[2*i+1].w));
            const uint32_t doff = (uint32_t)(a_row * 128) +
                                  (((uint32_t)(a_half * 64 + i * 16)) ^ a_xr);
            *reinterpret_cast<uint4*>(sA + doff) = o;
        }
    };

    // ---- compute-warp addressing: 2m x 6n grid, warp tile 32m x 64n ----
    const int cw = wid;                      // 0..11 for compute
    const int wm = cw / 6;                   // 0..1
    const int wn = cw % 6;                   // 0..5
    const int mb = wm * 32;
    const int nb = wn * 64;

    const int ri = lane & 15;
    const uint32_t sega = (uint32_t)((lane >> 4) << 4);
    const uint32_t xpa  = (uint32_t)((ri & 7) << 4);
    const uint32_t a_root = (uint32_t)((mb + ri) * 128);

    const int rb = (lane & 7) + (((lane >> 4) & 1) << 3);
    const uint32_t segb = (uint32_t)(((lane >> 3) & 1) << 4);
    const uint32_t xpb  = (uint32_t)((rb & 7) << 4);
    const uint32_t b_root = (uint32_t)A_ST + (uint32_t)((nb + rb) * 128);

    float acc[2][8][4];
#pragma unroll
    for (int t = 0; t < 2; t++)
#pragma unroll
        for (int j = 0; j < 8; j++)
#pragma unroll
            for (int q = 0; q < 4; q++) acc[t][j][q] = 0.0f;

    // ---- prologue: copy warps fill stages 0 and 1 ----
    if (is_copy) {
        copyA(0); cpB(0); CP_COMMIT();
        copyA(1); cpB(1); CP_COMMIT();
        CP_WAIT0();
    }
    __syncthreads();

    for (int kc = 0; kc < KCHUNKS; kc++) {
        if (is_copy) {
            if (kc + 2 < KCHUNKS) {
                copyA(kc + 2);               // LDG stall overlapped with MMAs
                cpB(kc + 2);
                CP_COMMIT();
                CP_WAIT1();                  // ensure stage kc+1 B complete
            } else {
                CP_WAIT0();
            }
        } else {
            const uint32_t stb = sb + (uint32_t)((kc % 3) * STAGE_BYTES);
#pragma unroll
            for (int s = 0; s < 4; s++) {
                const uint32_t sbytes = (uint32_t)(s * 32);
                uint32_t af[2][4];
                ldsm4(af[0], stb + a_root + ((sbytes + sega) ^ xpa));
                ldsm4(af[1], stb + a_root + 2048u + ((sbytes + sega) ^ xpa));
#pragma unroll
                for (int jp = 0; jp < 4; jp++) {
                    uint32_t bf[4];
                    ldsm4(bf, stb + b_root + (uint32_t)(jp * 2048) + ((sbytes + segb) ^ xpb));
                    mma_f16(acc[0][2 * jp],     af[0], bf);
                    mma_f16(acc[0][2 * jp + 1], af[0], bf + 2);
                    mma_f16(acc[1][2 * jp],     af[1], bf);
                    mma_f16(acc[1][2 * jp + 1], af[1], bf + 2);
                }
            }
        }
        __syncthreads();   // stage kc+1 visible; ring slot (kc+2)%3 safe to reuse
    }

    // ---- spill gi to smem (64 x ROWP), compute warps only ----
    float* gi = reinterpret_cast<float*>(sb_ptr);
    if (!is_copy) {
        const int r0 = mb + (lane >> 2);
        const int c0 = nb + 2 * (lane & 3);
#pragma unroll
        for (int t = 0; t < 2; t++) {
            const int row = r0 + t * 16;
#pragma unroll
            for (int j = 0; j < 8; j++) {
                const int col = c0 + j * 8;
                gi[row * ROWP + col]           = acc[t][j][0];
                gi[row * ROWP + col + 1]       = acc[t][j][1];
                gi[(row + 8) * ROWP + col]     = acc[t][j][2];
                gi[(row + 8) * ROWP + col + 1] = acc[t][j][3];
            }
        }
    }
    __syncthreads();

    // ---- fused gate epilogue: 8 threads per row; biases from gmem (L2) ----
    {
        const int row = tid >> 3;
        const int oct = tid & 7;
        const float* gr = gi + row * ROWP;
        float a = 0.0f;
#pragma unroll 4
        for (int k = 0; k < 16; k++) {
            const int g = oct * 16 + k;
            const float xr = gr[g] + b_ih[g] + b_hh[g];
            const float xz = gr[128 + g] + b_ih[128 + g] + b_hh[128 + g];
            const float r  = 1.0f / (1.0f + __expf(-xr));
            const float zc = 1.0f / (1.0f + __expf(xz));          // 1 - z
            const float xn = gr[256 + g] + b_ih[256 + g] + r * b_hh[256 + g];
            const float e  = __expf(-2.0f * fabsf(xn));
            float th = __fdividef(1.0f - e, 1.0f + e);
            th = copysignf(th, xn);
            a += lin_w[g] * zc * th;
        }
        a += __shfl_xor_sync(0xffffffffu, a, 1);
        a += __shfl_xor_sync(0xffffffffu, a, 2);
        a += __shfl_xor_sync(0xffffffffu, a, 4);
        if (oct == 0) out[m0 + row] = a + lin_b[0];
    }
}

extern "C" void kernel_launch(void* const* d_in, const int* in_sizes, int n_in,
                              void* d_out, int out_size) {
    const float* x     = (const float*)d_in[0];
    const float* w_ih  = (const float*)d_in[1];
    // d_in[2] = weight_hh: mathematically dead (hidden state is always zero)
    const float* b_ih  = (const float*)d_in[3];
    const float* b_hh  = (const float*)d_in[4];
    const float* lin_w = (const float*)d_in[5];
    const float* lin_b = (const float*)d_in[6];
    float* out = (float*)d_out;

    wconv_kernel<<<192, 256>>>(w_ih);   // 384*1024 / (256*8)

    cudaFuncSetAttribute(ping_head_kernel,
                         cudaFuncAttributeMaxDynamicSharedMemorySize, SMEM_DYN);
    ping_head_kernel<<<1024, 512, SMEM_DYN>>>(x, b_ih, b_hh, lin_w, lin_b, out);
}